// round 1
// baseline (speedup 1.0000x reference)
#include <cuda_runtime.h>
#include <cstdint>

// PolyLoss: polygon rasterization IoU loss + L1 reg.
// B=4, K=128, C=32 (V=16 vertices), H=W=128, OFF=32.
//
// Strategy: one block per (b,k) polygon pair (512 blocks, 128 threads).
// Thread t rasterizes row py=t for BOTH pred and gt polygons as 128-bit
// masks (2x uint64). Each crossing edge toggles prefix bits [0, ceil(xint)).
// inter = popc(p & g); counts via popc. Block-reduce -> iou -> atomics.

#define NB 4
#define NK 128
#define NC 32
#define NV 16
#define NH 128
#define NW 128

__device__ float g_acc[3];  // [0]=sum(iou*mask), [1]=sum_reg, [2]=msum

__global__ void init_kernel() {
    g_acc[0] = 0.f; g_acc[1] = 0.f; g_acc[2] = 0.f;
}

__device__ __forceinline__ void toggle_prefix(float xint,
                                              unsigned long long& lo,
                                              unsigned long long& hi) {
    // count of integer px in [0,128) with (float)px < xint  ==  clamp(ceil(xint),0,128)
    float c = ceilf(xint);
    if (c <= 0.f) return;
    if (c >= 128.f) { lo ^= ~0ull; hi ^= ~0ull; return; }
    int n = (int)c;
    if (n >= 64) { lo ^= ~0ull; hi ^= (n == 64) ? 0ull : ((1ull << (n - 64)) - 1ull); }
    else         { lo ^= (1ull << n) - 1ull; }
}

__global__ void __launch_bounds__(128) poly_kernel(
    const float* __restrict__ output,   // (B,C,H,W)
    const int*   __restrict__ mask,     // (B,K)
    const int*   __restrict__ ind,      // (B,K)
    const float* __restrict__ target)   // (B,K,C)
{
    const int poly = blockIdx.x;            // 0..511
    const int b = poly / NK, k = poly % NK;
    const int tid = threadIdx.x;

    __shared__ float sp[NC];   // gathered pred (raw, no offset)
    __shared__ float sg[NC];   // target (raw)
    __shared__ int   s_red[3][4];

    if (tid < NC) {
        int idx = ind[b * NK + k];
        sp[tid] = output[((b * NC + tid) * (NH * NW)) + idx];
        sg[tid] = target[(b * NK + k) * NC + tid];
    }
    __syncthreads();

    const float maskf = (float)mask[b * NK + k];
    const float py = (float)tid;

    unsigned long long plo = 0, phi = 0, glo = 0, ghi = 0;

    #pragma unroll
    for (int v = 0; v < NV; v++) {
        const int v2 = (v + 1) & (NV - 1);
        // ---- pred polygon ----
        {
            float x1 = sp[2 * v]      + 32.f;
            float y1 = sp[2 * v + 1]  + 32.f;
            float x2 = sp[2 * v2]     + 32.f;
            float y2 = sp[2 * v2 + 1] + 32.f;
            bool crossing = ((y1 <= py) && (y2 > py)) || ((y2 <= py) && (y1 > py));
            if (crossing) {
                float dy = y2 - y1;
                float denom = (dy == 0.f) ? 1.f : dy;
                float xint = x1 + (py - y1) * ((x2 - x1) / denom);
                toggle_prefix(xint, plo, phi);
            }
        }
        // ---- gt polygon ----
        {
            float x1 = sg[2 * v]      + 32.f;
            float y1 = sg[2 * v + 1]  + 32.f;
            float x2 = sg[2 * v2]     + 32.f;
            float y2 = sg[2 * v2 + 1] + 32.f;
            bool crossing = ((y1 <= py) && (y2 > py)) || ((y2 <= py) && (y1 > py));
            if (crossing) {
                float dy = y2 - y1;
                float denom = (dy == 0.f) ? 1.f : dy;
                float xint = x1 + (py - y1) * ((x2 - x1) / denom);
                toggle_prefix(xint, glo, ghi);
            }
        }
    }

    int inter = __popcll(plo & glo) + __popcll(phi & ghi);
    int cp    = __popcll(plo) + __popcll(phi);
    int cg    = __popcll(glo) + __popcll(ghi);

    // block reduction (4 warps)
    const int lane = tid & 31, wid = tid >> 5;
    #pragma unroll
    for (int o = 16; o; o >>= 1) {
        inter += __shfl_down_sync(0xffffffffu, inter, o);
        cp    += __shfl_down_sync(0xffffffffu, cp, o);
        cg    += __shfl_down_sync(0xffffffffu, cg, o);
    }
    if (lane == 0) { s_red[0][wid] = inter; s_red[1][wid] = cp; s_red[2][wid] = cg; }
    __syncthreads();

    if (tid == 0) {
        int ti = 0, tp = 0, tg = 0;
        #pragma unroll
        for (int w = 0; w < 4; w++) { ti += s_red[0][w]; tp += s_red[1][w]; tg += s_red[2][w]; }
        float fi = (float)ti;
        float un = (float)(tp + tg) - fi;
        float iou = fi / (un + 1e-6f);
        atomicAdd(&g_acc[0], iou * maskf);
        atomicAdd(&g_acc[2], maskf);
    }

    // loss_reg: warp 0, one channel per lane
    if (tid < NC) {
        float d = fabsf(sp[tid] * maskf - sg[tid] * maskf);
        #pragma unroll
        for (int o = 16; o; o >>= 1) d += __shfl_down_sync(0xffffffffu, d, o);
        if (tid == 0) atomicAdd(&g_acc[1], d);
    }
}

__global__ void finalize_kernel(float* out) {
    float msum = g_acc[2];
    float inv = 1.f / (msum + 1e-6f);
    out[0] = (1.f - g_acc[0] * inv) + g_acc[1] * inv;
}

extern "C" void kernel_launch(void* const* d_in, const int* in_sizes, int n_in,
                              void* d_out, int out_size) {
    const float* output = (const float*)d_in[0];
    const int*   mask   = (const int*)d_in[1];
    const int*   ind    = (const int*)d_in[2];
    const float* target = (const float*)d_in[3];
    // d_in[4] = freq_mask (unused by the reference computation)
    float* out = (float*)d_out;

    init_kernel<<<1, 1>>>();
    poly_kernel<<<NB * NK, 128>>>(output, mask, ind, target);
    finalize_kernel<<<1, 1>>>(out);
}

// round 2
// speedup vs baseline: 1.0837x; 1.0837x over previous
#include <cuda_runtime.h>
#include <cstdint>

// PolyLoss: polygon rasterization IoU loss + L1 reg — single-launch version.
// B=4, K=128, C=32 (V=16 vertices), H=W=128, OFF=32.
//
// One block per (b,k) polygon pair (512 blocks, 128 threads).
// Thread t rasterizes row py=t for pred and gt polygons as 128-bit masks.
// Block partials go to g_part[]; the last block (threadfence reduction
// pattern) folds 512 partials into the scalar output and resets the counter,
// so the kernel is graph-replayable with no init/finalize launches.

#define NB 4
#define NK 128
#define NC 32
#define NV 16
#define NH 128
#define NW 128
#define NBLK (NB * NK)   // 512

__device__ float4 g_part[NBLK];          // x=iou*m, y=reg, z=maskf
__device__ unsigned int g_count = 0;     // reset by last block each launch

__device__ __forceinline__ void toggle_prefix(float xint,
                                              unsigned long long& lo,
                                              unsigned long long& hi) {
    // #{px in [0,128) : (float)px < xint} == clamp(ceil(xint), 0, 128)
    float c = ceilf(xint);
    if (c <= 0.f) return;
    if (c >= 128.f) { lo ^= ~0ull; hi ^= ~0ull; return; }
    int n = (int)c;
    if (n >= 64) { lo ^= ~0ull; hi ^= (n == 64) ? 0ull : ((1ull << (n - 64)) - 1ull); }
    else         { lo ^= (1ull << n) - 1ull; }
}

__global__ void __launch_bounds__(128) poly_kernel(
    const float* __restrict__ output,   // (B,C,H,W)
    const int*   __restrict__ mask,     // (B,K)
    const int*   __restrict__ ind,      // (B,K)
    const float* __restrict__ target,   // (B,K,C)
    float*       __restrict__ out)
{
    const int poly = blockIdx.x;            // 0..511
    const int b = poly >> 7, k = poly & 127;
    const int tid = threadIdx.x;

    __shared__ float sp[NC];   // gathered pred (raw)
    __shared__ float sg[NC];   // target (raw)
    __shared__ int   s_red[3][4];
    __shared__ bool  s_last;

    if (tid < NC) {
        int idx = ind[b * NK + k];
        sp[tid] = output[((b * NC + tid) * (NH * NW)) + idx];
        sg[tid] = target[(b * NK + k) * NC + tid];
    }
    __syncthreads();

    const float maskf = (float)mask[b * NK + k];
    const float py = (float)tid;

    unsigned long long plo = 0, phi = 0, glo = 0, ghi = 0;

    #pragma unroll
    for (int v = 0; v < NV; v++) {
        const int v2 = (v + 1) & (NV - 1);
        {   // pred
            float x1 = sp[2 * v]      + 32.f;
            float y1 = sp[2 * v + 1]  + 32.f;
            float x2 = sp[2 * v2]     + 32.f;
            float y2 = sp[2 * v2 + 1] + 32.f;
            bool crossing = ((y1 <= py) && (y2 > py)) || ((y2 <= py) && (y1 > py));
            if (crossing) {
                float dy = y2 - y1;
                float denom = (dy == 0.f) ? 1.f : dy;
                float xint = x1 + (py - y1) * ((x2 - x1) / denom);
                toggle_prefix(xint, plo, phi);
            }
        }
        {   // gt
            float x1 = sg[2 * v]      + 32.f;
            float y1 = sg[2 * v + 1]  + 32.f;
            float x2 = sg[2 * v2]     + 32.f;
            float y2 = sg[2 * v2 + 1] + 32.f;
            bool crossing = ((y1 <= py) && (y2 > py)) || ((y2 <= py) && (y1 > py));
            if (crossing) {
                float dy = y2 - y1;
                float denom = (dy == 0.f) ? 1.f : dy;
                float xint = x1 + (py - y1) * ((x2 - x1) / denom);
                toggle_prefix(xint, glo, ghi);
            }
        }
    }

    int inter = __popcll(plo & glo) + __popcll(phi & ghi);
    int cp    = __popcll(plo) + __popcll(phi);
    int cg    = __popcll(glo) + __popcll(ghi);

    const int lane = tid & 31, wid = tid >> 5;
    #pragma unroll
    for (int o = 16; o; o >>= 1) {
        inter += __shfl_down_sync(0xffffffffu, inter, o);
        cp    += __shfl_down_sync(0xffffffffu, cp, o);
        cg    += __shfl_down_sync(0xffffffffu, cg, o);
    }
    if (lane == 0) { s_red[0][wid] = inter; s_red[1][wid] = cp; s_red[2][wid] = cg; }

    // loss_reg partial: warp 0, one channel per lane
    float reg = 0.f;
    if (tid < NC) {
        float d = fabsf(sp[tid] * maskf - sg[tid] * maskf);
        #pragma unroll
        for (int o = 16; o; o >>= 1) d += __shfl_down_sync(0xffffffffu, d, o);
        reg = d;   // valid at lane 0 of warp 0
    }
    __syncthreads();

    if (tid == 0) {
        int ti = 0, tp = 0, tg = 0;
        #pragma unroll
        for (int w = 0; w < 4; w++) { ti += s_red[0][w]; tp += s_red[1][w]; tg += s_red[2][w]; }
        float fi = (float)ti;
        float un = (float)(tp + tg) - fi;
        float iou = fi / (un + 1e-6f);
        g_part[poly] = make_float4(iou * maskf, reg, maskf, 0.f);
        __threadfence();
        unsigned int old = atomicAdd(&g_count, 1u);
        s_last = (old == NBLK - 1);
    }
    __syncthreads();

    if (s_last) {
        // final reduction over 512 partials: 128 threads x 4 entries
        float a0 = 0.f, a1 = 0.f, a2 = 0.f;
        #pragma unroll
        for (int i = 0; i < NBLK / 128; i++) {
            float4 p = g_part[tid + i * 128];
            a0 += p.x; a1 += p.y; a2 += p.z;
        }
        #pragma unroll
        for (int o = 16; o; o >>= 1) {
            a0 += __shfl_down_sync(0xffffffffu, a0, o);
            a1 += __shfl_down_sync(0xffffffffu, a1, o);
            a2 += __shfl_down_sync(0xffffffffu, a2, o);
        }
        __shared__ float s_f[3][4];
        if (lane == 0) { s_f[0][wid] = a0; s_f[1][wid] = a1; s_f[2][wid] = a2; }
        __syncthreads();
        if (tid == 0) {
            float t0 = 0.f, t1 = 0.f, t2 = 0.f;
            #pragma unroll
            for (int w = 0; w < 4; w++) { t0 += s_f[0][w]; t1 += s_f[1][w]; t2 += s_f[2][w]; }
            float inv = 1.f / (t2 + 1e-6f);
            out[0] = (1.f - t0 * inv) + t1 * inv;
            g_count = 0;   // reset for next graph replay
        }
    }
}

extern "C" void kernel_launch(void* const* d_in, const int* in_sizes, int n_in,
                              void* d_out, int out_size) {
    const float* output = (const float*)d_in[0];
    const int*   mask   = (const int*)d_in[1];
    const int*   ind    = (const int*)d_in[2];
    const float* target = (const float*)d_in[3];
    float* out = (float*)d_out;

    poly_kernel<<<NBLK, 128>>>(output, mask, ind, target, out);
}

// round 3
// speedup vs baseline: 1.4472x; 1.3354x over previous
#include <cuda_runtime.h>
#include <cstdint>

// PolyLoss single-launch, slope-precompute version.
// B=4, K=128, C=32 (V=16), H=W=128, OFF=32.
// One block per (b,k): 128 threads, thread t = raster row py=t.
// 32 edges (16 pred + 16 gt) precomputed once per block (x1,y1,y2,slope),
// then a branchless per-row prefix-XOR builds 128-bit row masks.

#define NB 4
#define NK 128
#define NC 32
#define NV 16
#define NH 128
#define NW 128
#define NBLK (NB * NK)   // 512

typedef unsigned long long ull;

__device__ float4 g_part[NBLK];          // x=iou*m, y=reg, z=maskf
__device__ unsigned int g_count = 0;     // reset by last block each launch

__device__ __forceinline__ ull prefix_lo(int n) {
    // n in [0,128]; bits [0, min(n,64))
    return (n >= 64) ? ~0ull : ((1ull << n) - 1ull);
}
__device__ __forceinline__ ull prefix_hi(int n) {
    return (n >= 128) ? ~0ull : ((n <= 64) ? 0ull : ((1ull << (n - 64)) - 1ull));
}

__global__ void __launch_bounds__(128) poly_kernel(
    const float* __restrict__ output,   // (B,C,H,W)
    const int*   __restrict__ mask,     // (B,K)
    const int*   __restrict__ ind,      // (B,K)
    const float* __restrict__ target,   // (B,K,C)
    float*       __restrict__ out)
{
    const int poly = blockIdx.x;            // 0..511
    const int b = poly >> 7, k = poly & 127;
    const int tid = threadIdx.x;

    __shared__ float s_xy[64];              // [0..31]=pred coords, [32..63]=gt coords
    __shared__ float e_x1[32], e_y1[32], e_y2[32], e_s[32];  // 16 pred + 16 gt edges
    __shared__ int   s_red[3][4];
    __shared__ float s_reg;
    __shared__ bool  s_last;

    if (tid < NC) {
        int idx = ind[b * NK + k];
        s_xy[tid]      = output[((b * NC + tid) * (NH * NW)) + idx];
        s_xy[32 + tid] = target[(b * NK + k) * NC + tid];
    }
    __syncthreads();

    const float maskf = (float)mask[b * NK + k];

    // ---- edge precompute + reg-loss partial (threads 0..31) ----
    if (tid < 32) {
        const int base = (tid >> 4) << 5;   // 0 for pred edges, 32 for gt edges
        const int v  = tid & 15;
        const int v2 = (v + 1) & 15;
        float x1 = s_xy[base + 2 * v]      + 32.f;
        float y1 = s_xy[base + 2 * v + 1]  + 32.f;
        float x2 = s_xy[base + 2 * v2]     + 32.f;
        float y2 = s_xy[base + 2 * v2 + 1] + 32.f;
        float dy = y2 - y1;
        float denom = (dy == 0.f) ? 1.f : dy;
        e_x1[tid] = x1;
        e_y1[tid] = y1;
        e_y2[tid] = y2;
        e_s[tid]  = (x2 - x1) / denom;

        // reg-loss: |pred*m - target*m| per channel
        float d = fabsf(s_xy[tid] * maskf - s_xy[32 + tid] * maskf);
        #pragma unroll
        for (int o = 16; o; o >>= 1) d += __shfl_down_sync(0xffffffffu, d, o);
        if (tid == 0) s_reg = d;
    }
    __syncthreads();

    const float py = (float)tid;
    ull plo = 0, phi = 0, glo = 0, ghi = 0;

    #pragma unroll
    for (int e = 0; e < 16; e++) {          // pred edges
        float y1 = e_y1[e], y2 = e_y2[e];
        bool crossing = (y1 <= py) != (y2 <= py);
        float xint = fmaf(py - y1, e_s[e], e_x1[e]);
        int n = (int)fminf(fmaxf(ceilf(xint), 0.f), 128.f);
        n = crossing ? n : 0;
        plo ^= prefix_lo(n);
        phi ^= prefix_hi(n);
    }
    #pragma unroll
    for (int e = 16; e < 32; e++) {         // gt edges
        float y1 = e_y1[e], y2 = e_y2[e];
        bool crossing = (y1 <= py) != (y2 <= py);
        float xint = fmaf(py - y1, e_s[e], e_x1[e]);
        int n = (int)fminf(fmaxf(ceilf(xint), 0.f), 128.f);
        n = crossing ? n : 0;
        glo ^= prefix_lo(n);
        ghi ^= prefix_hi(n);
    }

    int inter = __popcll(plo & glo) + __popcll(phi & ghi);
    int cp    = __popcll(plo) + __popcll(phi);
    int cg    = __popcll(glo) + __popcll(ghi);

    const int lane = tid & 31, wid = tid >> 5;
    #pragma unroll
    for (int o = 16; o; o >>= 1) {
        inter += __shfl_down_sync(0xffffffffu, inter, o);
        cp    += __shfl_down_sync(0xffffffffu, cp, o);
        cg    += __shfl_down_sync(0xffffffffu, cg, o);
    }
    if (lane == 0) { s_red[0][wid] = inter; s_red[1][wid] = cp; s_red[2][wid] = cg; }
    __syncthreads();

    if (tid == 0) {
        int ti = 0, tp = 0, tg = 0;
        #pragma unroll
        for (int w = 0; w < 4; w++) { ti += s_red[0][w]; tp += s_red[1][w]; tg += s_red[2][w]; }
        float fi = (float)ti;
        float un = (float)(tp + tg) - fi;
        float iou = fi / (un + 1e-6f);
        g_part[poly] = make_float4(iou * maskf, s_reg, maskf, 0.f);
        __threadfence();
        unsigned int old = atomicAdd(&g_count, 1u);
        s_last = (old == NBLK - 1);
    }
    __syncthreads();

    if (s_last) {
        float a0 = 0.f, a1 = 0.f, a2 = 0.f;
        #pragma unroll
        for (int i = 0; i < NBLK / 128; i++) {
            float4 p = g_part[tid + i * 128];
            a0 += p.x; a1 += p.y; a2 += p.z;
        }
        #pragma unroll
        for (int o = 16; o; o >>= 1) {
            a0 += __shfl_down_sync(0xffffffffu, a0, o);
            a1 += __shfl_down_sync(0xffffffffu, a1, o);
            a2 += __shfl_down_sync(0xffffffffu, a2, o);
        }
        __shared__ float s_f[3][4];
        if (lane == 0) { s_f[0][wid] = a0; s_f[1][wid] = a1; s_f[2][wid] = a2; }
        __syncthreads();
        if (tid == 0) {
            float t0 = 0.f, t1 = 0.f, t2 = 0.f;
            #pragma unroll
            for (int w = 0; w < 4; w++) { t0 += s_f[0][w]; t1 += s_f[1][w]; t2 += s_f[2][w]; }
            float inv = 1.f / (t2 + 1e-6f);
            out[0] = (1.f - t0 * inv) + t1 * inv;
            g_count = 0;   // reset for next graph replay
        }
    }
}

extern "C" void kernel_launch(void* const* d_in, const int* in_sizes, int n_in,
                              void* d_out, int out_size) {
    const float* output = (const float*)d_in[0];
    const int*   mask   = (const int*)d_in[1];
    const int*   ind    = (const int*)d_in[2];
    const float* target = (const float*)d_in[3];
    float* out = (float*)d_out;

    poly_kernel<<<NBLK, 128>>>(output, mask, ind, target, out);
}